// round 7
// baseline (speedup 1.0000x reference)
#include <cuda_runtime.h>
#include <math.h>
#include <stdint.h>

// Problem constants
#define BATCH 2
#define NSEQ 2048
#define DIM 1024
#define HEADS 16
#define DHEAD 64
#define INNER (HEADS * DHEAD)      // 1024
#define QKV_W (3 * INNER)          // 3072
#define ROWS (BATCH * NSEQ)        // 4096
#define SCALE 0.125f               // 64^-0.5
#define LN_EPS 1e-5f
#define LOG2E 1.4426950408889634f

// Scratch (device globals: allocation-free rule)
__device__ float g_xn[ROWS * DIM];         // 16 MB (tf32-rounded)
__device__ float g_qkv[ROWS * QKV_W];      // 48 MB
__device__ float g_attn[ROWS * INNER];     // 16 MB (tf32-rounded)
__device__ float g_wqkvT[QKV_W * DIM];     // 12 MB (tf32-rounded, transposed [N][K])
__device__ float g_woutT[DIM * INNER];     //  4 MB (tf32-rounded, transposed [N][K])

// ---------------------------------------------------------------------------
// helpers
// ---------------------------------------------------------------------------
__device__ __forceinline__ uint32_t cvt_tf32(float f) {
    uint32_t r;
    asm("cvt.rna.tf32.f32 %0, %1;" : "=r"(r) : "f"(f));
    return r;
}
__device__ __forceinline__ float rnd_tf32(float f) {
    return __uint_as_float(cvt_tf32(f));
}
__device__ __forceinline__ float exp2_fast(float x) {
    float y;
    asm("ex2.approx.ftz.f32 %0, %1;" : "=f"(y) : "f"(x));
    return y;
}
__device__ __forceinline__ float trunc_tf32(float f) {
    return __uint_as_float(__float_as_uint(f) & 0xFFFFE000u);
}

__device__ __forceinline__ void mma_tf32(float c[4],
                                         uint32_t a0, uint32_t a1, uint32_t a2, uint32_t a3,
                                         uint32_t b0, uint32_t b1) {
    asm volatile(
        "mma.sync.aligned.m16n8k8.row.col.f32.tf32.tf32.f32 "
        "{%0,%1,%2,%3}, {%4,%5,%6,%7}, {%8,%9}, {%0,%1,%2,%3};"
        : "+f"(c[0]), "+f"(c[1]), "+f"(c[2]), "+f"(c[3])
        : "r"(a0), "r"(a1), "r"(a2), "r"(a3), "r"(b0), "r"(b1));
}

__device__ __forceinline__ void ldsm_x4(uint32_t r[4], uint32_t addr) {
    asm volatile("ldmatrix.sync.aligned.m8n8.x4.shared.b16 {%0,%1,%2,%3}, [%4];"
                 : "=r"(r[0]), "=r"(r[1]), "=r"(r[2]), "=r"(r[3]) : "r"(addr));
}

__device__ __forceinline__ void cp_async16(uint32_t dst, const void* src) {
    asm volatile("cp.async.cg.shared.global [%0], [%1], 16;" :: "r"(dst), "l"(src));
}
__device__ __forceinline__ void cp_commit() {
    asm volatile("cp.async.commit_group;");
}
template <int N>
__device__ __forceinline__ void cp_wait() {
    asm volatile("cp.async.wait_group %0;" :: "n"(N));
}

// ---------------------------------------------------------------------------
// transpose + tf32-round: src [R][C] -> dst [C][R]. R,C multiples of 32.
// ---------------------------------------------------------------------------
__global__ __launch_bounds__(256) void transpose_round_kernel(
    const float* __restrict__ src, float* __restrict__ dst, int R, int C)
{
    __shared__ float t[32][33];
    const int bx = blockIdx.x * 32;
    const int by = blockIdx.y * 32;
    const int tx = threadIdx.x;
    const int ty = threadIdx.y;

    #pragma unroll
    for (int i = 0; i < 4; i++)
        t[ty + i * 8][tx] = src[(size_t)(by + ty + i * 8) * C + bx + tx];
    __syncthreads();
    #pragma unroll
    for (int i = 0; i < 4; i++)
        dst[(size_t)(bx + ty + i * 8) * R + by + tx] = rnd_tf32(t[tx][ty + i * 8]);
}

// ---------------------------------------------------------------------------
// LayerNorm: one block per row, 256 threads, float4; emits tf32-rounded xn
// ---------------------------------------------------------------------------
__global__ __launch_bounds__(256) void ln_kernel(
    const float* __restrict__ x,
    const float* __restrict__ gamma,
    const float* __restrict__ beta,
    float* __restrict__ xn)
{
    __shared__ float red[8];
    const int row = blockIdx.x;
    const int tid = threadIdx.x;
    const float* xr = x + (size_t)row * DIM;

    float4 v = *(const float4*)(xr + tid * 4);

    float s = v.x + v.y + v.z + v.w;
    #pragma unroll
    for (int o = 16; o > 0; o >>= 1) s += __shfl_xor_sync(0xffffffffu, s, o);
    if ((tid & 31) == 0) red[tid >> 5] = s;
    __syncthreads();
    if (tid < 8) {
        float t = red[tid];
        #pragma unroll
        for (int o = 4; o > 0; o >>= 1) t += __shfl_xor_sync(0xffu, t, o);
        if (tid == 0) red[0] = t;
    }
    __syncthreads();
    const float mu = red[0] * (1.0f / DIM);
    __syncthreads();

    float d0 = v.x - mu, d1 = v.y - mu, d2 = v.z - mu, d3 = v.w - mu;
    float sq = d0 * d0 + d1 * d1 + d2 * d2 + d3 * d3;
    #pragma unroll
    for (int o = 16; o > 0; o >>= 1) sq += __shfl_xor_sync(0xffffffffu, sq, o);
    if ((tid & 31) == 0) red[tid >> 5] = sq;
    __syncthreads();
    if (tid < 8) {
        float t = red[tid];
        #pragma unroll
        for (int o = 4; o > 0; o >>= 1) t += __shfl_xor_sync(0xffu, t, o);
        if (tid == 0) red[0] = t;
    }
    __syncthreads();
    const float inv = rsqrtf(red[0] * (1.0f / DIM) + LN_EPS);

    const int c = tid * 4;
    float4 g = *(const float4*)(gamma + c);
    float4 b = *(const float4*)(beta + c);
    float4 o;
    o.x = rnd_tf32(d0 * inv * g.x + b.x);
    o.y = rnd_tf32(d1 * inv * g.y + b.y);
    o.z = rnd_tf32(d2 * inv * g.z + b.z);
    o.w = rnd_tf32(d3 * inv * g.w + b.w);
    *(float4*)(xn + (size_t)row * DIM + c) = o;
}

// ---------------------------------------------------------------------------
// TF32 tensor-core GEMM, ldmatrix fragments, cp.async 3-stage pipeline with
// EARLY prefetch (issued right after the barrier, before compute, so the
// awaited group has two compute phases of latency cover).
// C[M,N] = A[M,K] @ B^T; A is [M][K], B given transposed as [N][K]; both
// already tf32-rounded. Block 256 thr (8 warps, 4m x 2n), 128x128, BK=16.
// ---------------------------------------------------------------------------
#define LDT_ 20
#define STAGE_F (128 * LDT_)
__global__ __launch_bounds__(256) void tf32_gemm_ldsm(
    int M, int N, int K,
    const float* __restrict__ A,
    const float* __restrict__ B,
    float* __restrict__ C)
{
    __shared__ float As[3][STAGE_F];
    __shared__ float Bs[3][STAGE_F];

    const int tid  = threadIdx.x;
    const int warp = tid >> 5;
    const int lane = tid & 31;
    const int lr = lane >> 2;
    const int lc = lane & 3;

    const int wm = (warp & 3) * 32;
    const int wn = (warp >> 2) * 64;

    A += (size_t)blockIdx.y * 128 * K;
    B += (size_t)blockIdx.x * 128 * K;
    C += (size_t)blockIdx.y * 128 * N + blockIdx.x * 128;

    const int r0 = tid >> 2;
    const int k0 = (tid & 3) * 4;

    const uint32_t asBase = (uint32_t)__cvta_generic_to_shared(As);
    const uint32_t bsBase = (uint32_t)__cvta_generic_to_shared(Bs);

    const int nSlab = K / 16;

    auto load_slab = [&](int s, int buf) {
        const int gk = s * 16 + k0;
        const uint32_t ad = asBase + (uint32_t)(buf * STAGE_F * 4);
        const uint32_t bd = bsBase + (uint32_t)(buf * STAGE_F * 4);
        cp_async16(ad + (uint32_t)((r0 * LDT_ + k0) * 4),        A + (size_t)r0 * K + gk);
        cp_async16(ad + (uint32_t)(((r0 + 64) * LDT_ + k0) * 4), A + (size_t)(r0 + 64) * K + gk);
        cp_async16(bd + (uint32_t)((r0 * LDT_ + k0) * 4),        B + (size_t)r0 * K + gk);
        cp_async16(bd + (uint32_t)(((r0 + 64) * LDT_ + k0) * 4), B + (size_t)(r0 + 64) * K + gk);
    };

    const int aoff = (wm + (lane & 15)) * LDT_ + ((lane >> 4) << 2);
    const int boff = (wn + ((lane >> 4) << 3) + (lane & 7)) * LDT_ + (((lane >> 3) & 1) << 2);

    float acc[2][8][4] = {};

    load_slab(0, 0); cp_commit();
    if (nSlab > 1) load_slab(1, 1);
    cp_commit();

    for (int s = 0; s < nSlab; s++) {
        const int cur = s % 3;
        cp_wait<1>();
        __syncthreads();

        // EARLY prefetch: buffer (s+2)%3 == (s-1)%3 is free (barrier proves
        // compute(s-1) finished). Issuing before compute gives the group two
        // full compute phases before it is awaited.
        if (s + 2 < nSlab) load_slab(s + 2, (s + 2) % 3);
        cp_commit();

        const uint32_t aStage = asBase + (uint32_t)(cur * STAGE_F * 4);
        const uint32_t bStage = bsBase + (uint32_t)(cur * STAGE_F * 4);

        #pragma unroll
        for (int ks = 0; ks < 16; ks += 8) {
            uint32_t afr[2][4];
            #pragma unroll
            for (int mi = 0; mi < 2; mi++)
                ldsm_x4(afr[mi], aStage + (uint32_t)((aoff + mi * 16 * LDT_ + ks) * 4));
            uint32_t bfr[4][4];
            #pragma unroll
            for (int j = 0; j < 4; j++)
                ldsm_x4(bfr[j], bStage + (uint32_t)((boff + j * 16 * LDT_ + ks) * 4));
            #pragma unroll
            for (int mi = 0; mi < 2; mi++)
                #pragma unroll
                for (int j = 0; j < 4; j++) {
                    mma_tf32(acc[mi][2 * j],     afr[mi][0], afr[mi][1], afr[mi][2], afr[mi][3],
                             bfr[j][0], bfr[j][1]);
                    mma_tf32(acc[mi][2 * j + 1], afr[mi][0], afr[mi][1], afr[mi][2], afr[mi][3],
                             bfr[j][2], bfr[j][3]);
                }
        }
    }

    #pragma unroll
    for (int mi = 0; mi < 2; mi++) {
        const int r = wm + 16 * mi + lr;
        #pragma unroll
        for (int ni = 0; ni < 8; ni++) {
            const int c0 = wn + 8 * ni + 2 * lc;
            *(float2*)(C + (size_t)r * N + c0)       = make_float2(acc[mi][ni][0], acc[mi][ni][1]);
            *(float2*)(C + (size_t)(r + 8) * N + c0) = make_float2(acc[mi][ni][2], acc[mi][ni][3]);
        }
    }
}

// ---------------------------------------------------------------------------
// FlashAttention, TF32 mma, exact (non-online) softmax.
// Block = 256 threads (8 warps), 128 query rows per block for one (b,h):
// halves K/V L2 traffic vs the 64-row version. Warp w owns rows 16w..16w+15.
// P is truncated to tf32 in-place in sfr; l sums the same truncated values.
// ---------------------------------------------------------------------------
__global__ __launch_bounds__(256) void attn_mma_kernel(
    const float* __restrict__ qkv,
    float* __restrict__ attn_out)
{
    const int bh = blockIdx.y;
    const int b = bh / HEADS;
    const int h = bh % HEADS;
    const int qbase = blockIdx.x * 128;
    const int warp = threadIdx.x >> 5;
    const int lane = threadIdx.x & 31;
    const int lr = lane >> 2;
    const int lc = lane & 3;

    __shared__ float Ks[64][72];
    __shared__ float Vs[64][68];

    const float* base = qkv + (size_t)b * NSEQ * QKV_W;
    const float NEG_INF = __int_as_float(0xff800000);
    const float QSCALE = SCALE * LOG2E;

    // warp's diagonal tile start (global key index)
    const int diagKt = qbase + ((warp & 4) << 4);

    uint32_t qa[8][4];
    {
        const int r0 = qbase + warp * 16 + lr;
        const float* q0 = base + (size_t)r0 * QKV_W + h * DHEAD;
        const float* q1 = q0 + (size_t)8 * QKV_W;
        #pragma unroll
        for (int s = 0; s < 8; s++) {
            const int d0 = 8 * s + 2 * lc;
            qa[s][0] = cvt_tf32(q0[d0] * QSCALE);
            qa[s][1] = cvt_tf32(q1[d0] * QSCALE);
            qa[s][2] = cvt_tf32(q0[d0 + 1] * QSCALE);
            qa[s][3] = cvt_tf32(q1[d0 + 1] * QSCALE);
        }
    }

    float oa[8][4] = {};
    float l0 = 0.0f, l1 = 0.0f;

    for (int kt = 0; kt < NSEQ; kt += 64) {
        __syncthreads();

        // cooperative K/V tile load: 1024 float4, 4 per thread
        #pragma unroll
        for (int it = 0; it < 4; it++) {
            const int idx = threadIdx.x + it * 256;
            const int r = idx >> 4;
            const int c = (idx & 15) * 4;
            const float* kr = base + (size_t)(kt + r) * QKV_W + INNER + h * DHEAD + c;
            const float* vr = kr + INNER;
            float4 kv = *(const float4*)kr;
            float4 vv = *(const float4*)vr;
            uint4 ku = make_uint4(cvt_tf32(kv.x), cvt_tf32(kv.y), cvt_tf32(kv.z), cvt_tf32(kv.w));
            uint4 vu = make_uint4(cvt_tf32(vv.x), cvt_tf32(vv.y), cvt_tf32(vv.z), cvt_tf32(vv.w));
            *(uint4*)(&Ks[r][c]) = ku;
            *(uint4*)(&Vs[r][c]) = vu;
        }
        __syncthreads();

        // ---- S' = (Q*scale*log2e) @ K^T ----
        float sfr[8][4] = {};
        #pragma unroll
        for (int s = 0; s < 8; s++) {
            #pragma unroll
            for (int n = 0; n < 8; n++) {
                float2 kb = *(const float2*)(&Ks[8 * n + lr][8 * s + 2 * lc]);
                mma_tf32(sfr[n], qa[s][0], qa[s][1], qa[s][2], qa[s][3],
                         __float_as_uint(kb.x), __float_as_uint(kb.y));
            }
        }

        // ---- diagonal mask (warp-local diagonal tile) ----
        if (kt == diagKt) {
            const int rloc0 = 16 * (warp & 3) + lr;
            const int rloc1 = rloc0 + 8;
            #pragma unroll
            for (int n = 0; n < 8; n++) {
                const int col0 = 8 * n + 2 * lc;
                if (col0 == rloc0)     sfr[n][0] = NEG_INF;
                if (col0 + 1 == rloc0) sfr[n][1] = NEG_INF;
                if (col0 == rloc1)     sfr[n][2] = NEG_INF;
                if (col0 + 1 == rloc1) sfr[n][3] = NEG_INF;
            }
        }

        // ---- P = trunc_tf32(exp2(S')) in place; l from same values ----
        #pragma unroll
        for (int n = 0; n < 8; n++) {
            sfr[n][0] = trunc_tf32(exp2_fast(sfr[n][0]));
            sfr[n][1] = trunc_tf32(exp2_fast(sfr[n][1]));
            sfr[n][2] = trunc_tf32(exp2_fast(sfr[n][2]));
            sfr[n][3] = trunc_tf32(exp2_fast(sfr[n][3]));
            l0 += sfr[n][0] + sfr[n][1];
            l1 += sfr[n][2] + sfr[n][3];
        }

        // ---- O += P @ V ----
        #pragma unroll
        for (int s = 0; s < 8; s++) {
            const uint32_t a0 = __float_as_uint(sfr[s][0]);
            const uint32_t a1 = __float_as_uint(sfr[s][2]);
            const uint32_t a2 = __float_as_uint(sfr[s][1]);
            const uint32_t a3 = __float_as_uint(sfr[s][3]);
            #pragma unroll
            for (int n = 0; n < 8; n++) {
                const uint32_t vb0 = __float_as_uint(Vs[8 * s + 2 * lc][8 * n + lr]);
                const uint32_t vb1 = __float_as_uint(Vs[8 * s + 2 * lc + 1][8 * n + lr]);
                mma_tf32(oa[n], a0, a1, a2, a3, vb0, vb1);
            }
        }
    }

    l0 += __shfl_xor_sync(0xffffffffu, l0, 1);
    l0 += __shfl_xor_sync(0xffffffffu, l0, 2);
    l1 += __shfl_xor_sync(0xffffffffu, l1, 1);
    l1 += __shfl_xor_sync(0xffffffffu, l1, 2);
    const float inv0 = 1.0f / l0;
    const float inv1 = 1.0f / l1;

    const int row0 = qbase + 16 * warp + lr;
    float* o0 = attn_out + ((size_t)b * NSEQ + row0) * INNER + h * DHEAD;
    float* o1 = o0 + (size_t)8 * INNER;
    #pragma unroll
    for (int n = 0; n < 8; n++) {
        const int c = 8 * n + 2 * lc;
        *(float2*)(o0 + c) = make_float2(rnd_tf32(oa[n][0] * inv0), rnd_tf32(oa[n][1] * inv0));
        *(float2*)(o1 + c) = make_float2(rnd_tf32(oa[n][2] * inv1), rnd_tf32(oa[n][3] * inv1));
    }
}

// ---------------------------------------------------------------------------
extern "C" void kernel_launch(void* const* d_in, const int* in_sizes, int n_in,
                              void* d_out, int out_size)
{
    const float* x      = (const float*)d_in[0];
    const float* gamma  = (const float*)d_in[1];
    const float* beta   = (const float*)d_in[2];
    const float* w_qkv  = (const float*)d_in[3];
    const float* w_out  = (const float*)d_in[4];
    float* out = (float*)d_out;

    float *xn, *qkv, *attn, *wqkvT, *woutT;
    cudaGetSymbolAddress((void**)&xn,    g_xn);
    cudaGetSymbolAddress((void**)&qkv,   g_qkv);
    cudaGetSymbolAddress((void**)&attn,  g_attn);
    cudaGetSymbolAddress((void**)&wqkvT, g_wqkvT);
    cudaGetSymbolAddress((void**)&woutT, g_woutT);

    // 0) transpose + round weights: [K][N] -> [N][K] tf32
    {
        dim3 blk(32, 8);
        dim3 g1(QKV_W / 32, DIM / 32);
        transpose_round_kernel<<<g1, blk>>>(w_qkv, wqkvT, DIM, QKV_W);
        dim3 g2(DIM / 32, INNER / 32);
        transpose_round_kernel<<<g2, blk>>>(w_out, woutT, INNER, DIM);
    }

    // 1) LayerNorm (emits tf32-rounded)
    ln_kernel<<<ROWS, 256>>>(x, gamma, beta, xn);

    // 2) QKV projection: [4096,1024] @ [1024,3072]
    {
        dim3 grid(QKV_W / 128, ROWS / 128);
        tf32_gemm_ldsm<<<grid, 256>>>(ROWS, QKV_W, DIM, xn, wqkvT, qkv);
    }

    // 3) attention (128 q-rows per block)
    {
        dim3 grid(NSEQ / 128, BATCH * HEADS);
        attn_mma_kernel<<<grid, 256>>>(qkv, attn);
    }

    // 4) output projection: [4096,1024] @ [1024,1024]
    {
        dim3 grid(DIM / 128, ROWS / 128);
        tf32_gemm_ldsm<<<grid, 256>>>(ROWS, DIM, INNER, attn, woutT, out);
    }
}

// round 8
// speedup vs baseline: 1.0817x; 1.0817x over previous
#include <cuda_runtime.h>
#include <math.h>
#include <stdint.h>

// Problem constants
#define BATCH 2
#define NSEQ 2048
#define DIM 1024
#define HEADS 16
#define DHEAD 64
#define INNER (HEADS * DHEAD)      // 1024
#define QKV_W (3 * INNER)          // 3072
#define ROWS (BATCH * NSEQ)        // 4096
#define SCALE 0.125f               // 64^-0.5
#define LN_EPS 1e-5f
#define LOG2E 1.4426950408889634f

// Scratch (device globals: allocation-free rule)
__device__ float g_xn[ROWS * DIM];         // 16 MB (tf32-rounded)
__device__ float g_qkv[ROWS * QKV_W];      // 48 MB
__device__ float g_attn[ROWS * INNER];     // 16 MB (tf32-rounded)
__device__ float g_wqkvT[QKV_W * DIM];     // 12 MB (tf32-rounded, transposed [N][K])
__device__ float g_woutT[DIM * INNER];     //  4 MB (tf32-rounded, transposed [N][K])

// ---------------------------------------------------------------------------
// helpers
// ---------------------------------------------------------------------------
__device__ __forceinline__ uint32_t cvt_tf32(float f) {
    uint32_t r;
    asm("cvt.rna.tf32.f32 %0, %1;" : "=r"(r) : "f"(f));
    return r;
}
__device__ __forceinline__ float rnd_tf32(float f) {
    return __uint_as_float(cvt_tf32(f));
}
__device__ __forceinline__ float exp2_fast(float x) {
    float y;
    asm("ex2.approx.ftz.f32 %0, %1;" : "=f"(y) : "f"(x));
    return y;
}
__device__ __forceinline__ float trunc_tf32(float f) {
    return __uint_as_float(__float_as_uint(f) & 0xFFFFE000u);
}

__device__ __forceinline__ void mma_tf32(float c[4],
                                         uint32_t a0, uint32_t a1, uint32_t a2, uint32_t a3,
                                         uint32_t b0, uint32_t b1) {
    asm volatile(
        "mma.sync.aligned.m16n8k8.row.col.f32.tf32.tf32.f32 "
        "{%0,%1,%2,%3}, {%4,%5,%6,%7}, {%8,%9}, {%0,%1,%2,%3};"
        : "+f"(c[0]), "+f"(c[1]), "+f"(c[2]), "+f"(c[3])
        : "r"(a0), "r"(a1), "r"(a2), "r"(a3), "r"(b0), "r"(b1));
}

__device__ __forceinline__ void ldsm_x4(uint32_t r[4], uint32_t addr) {
    asm volatile("ldmatrix.sync.aligned.m8n8.x4.shared.b16 {%0,%1,%2,%3}, [%4];"
                 : "=r"(r[0]), "=r"(r[1]), "=r"(r[2]), "=r"(r[3]) : "r"(addr));
}

__device__ __forceinline__ void cp_async16(uint32_t dst, const void* src) {
    asm volatile("cp.async.cg.shared.global [%0], [%1], 16;" :: "r"(dst), "l"(src));
}
__device__ __forceinline__ void cp_commit() {
    asm volatile("cp.async.commit_group;");
}
template <int N>
__device__ __forceinline__ void cp_wait() {
    asm volatile("cp.async.wait_group %0;" :: "n"(N));
}

// ---------------------------------------------------------------------------
// transpose + tf32-round: src [R][C] -> dst [C][R]. R,C multiples of 32.
// ---------------------------------------------------------------------------
__global__ __launch_bounds__(256) void transpose_round_kernel(
    const float* __restrict__ src, float* __restrict__ dst, int R, int C)
{
    __shared__ float t[32][33];
    const int bx = blockIdx.x * 32;
    const int by = blockIdx.y * 32;
    const int tx = threadIdx.x;
    const int ty = threadIdx.y;

    #pragma unroll
    for (int i = 0; i < 4; i++)
        t[ty + i * 8][tx] = src[(size_t)(by + ty + i * 8) * C + bx + tx];
    __syncthreads();
    #pragma unroll
    for (int i = 0; i < 4; i++)
        dst[(size_t)(bx + ty + i * 8) * R + by + tx] = rnd_tf32(t[tx][ty + i * 8]);
}

// ---------------------------------------------------------------------------
// LayerNorm: one block per row, 256 threads, float4; emits tf32-rounded xn
// ---------------------------------------------------------------------------
__global__ __launch_bounds__(256) void ln_kernel(
    const float* __restrict__ x,
    const float* __restrict__ gamma,
    const float* __restrict__ beta,
    float* __restrict__ xn)
{
    __shared__ float red[8];
    const int row = blockIdx.x;
    const int tid = threadIdx.x;
    const float* xr = x + (size_t)row * DIM;

    float4 v = *(const float4*)(xr + tid * 4);

    float s = v.x + v.y + v.z + v.w;
    #pragma unroll
    for (int o = 16; o > 0; o >>= 1) s += __shfl_xor_sync(0xffffffffu, s, o);
    if ((tid & 31) == 0) red[tid >> 5] = s;
    __syncthreads();
    if (tid < 8) {
        float t = red[tid];
        #pragma unroll
        for (int o = 4; o > 0; o >>= 1) t += __shfl_xor_sync(0xffu, t, o);
        if (tid == 0) red[0] = t;
    }
    __syncthreads();
    const float mu = red[0] * (1.0f / DIM);
    __syncthreads();

    float d0 = v.x - mu, d1 = v.y - mu, d2 = v.z - mu, d3 = v.w - mu;
    float sq = d0 * d0 + d1 * d1 + d2 * d2 + d3 * d3;
    #pragma unroll
    for (int o = 16; o > 0; o >>= 1) sq += __shfl_xor_sync(0xffffffffu, sq, o);
    if ((tid & 31) == 0) red[tid >> 5] = sq;
    __syncthreads();
    if (tid < 8) {
        float t = red[tid];
        #pragma unroll
        for (int o = 4; o > 0; o >>= 1) t += __shfl_xor_sync(0xffu, t, o);
        if (tid == 0) red[0] = t;
    }
    __syncthreads();
    const float inv = rsqrtf(red[0] * (1.0f / DIM) + LN_EPS);

    const int c = tid * 4;
    float4 g = *(const float4*)(gamma + c);
    float4 b = *(const float4*)(beta + c);
    float4 o;
    o.x = rnd_tf32(d0 * inv * g.x + b.x);
    o.y = rnd_tf32(d1 * inv * g.y + b.y);
    o.z = rnd_tf32(d2 * inv * g.z + b.z);
    o.w = rnd_tf32(d3 * inv * g.w + b.w);
    *(float4*)(xn + (size_t)row * DIM + c) = o;
}

// ---------------------------------------------------------------------------
// TF32 tensor-core GEMM, ldmatrix fragments, cp.async DOUBLE buffer, BK=32.
// Halves the barrier count vs BK=16 and doubles compute run length between
// syncs (the kernel is barrier-paced at 2 CTAs/SM, not latency-bound).
// C[M,N] = A[M,K] @ B^T; A is [M][K], B given transposed as [N][K]; both
// already tf32-rounded. Block 256 thr (8 warps, 4m x 2n), 128x128 tile.
// Smem stride 36 floats: ldmatrix rows land on banks 4r..4r+3 -> all 32
// banks covered once (conflict-free); same for the cp.async stores.
// ---------------------------------------------------------------------------
#define LDT_ 36
#define STAGE_F (128 * LDT_)     // 4608 floats = 18 KB per tile per stage
__global__ __launch_bounds__(256) void tf32_gemm_ldsm(
    int M, int N, int K,
    const float* __restrict__ A,
    const float* __restrict__ B,
    float* __restrict__ C)
{
    __shared__ float As[2][STAGE_F];
    __shared__ float Bs[2][STAGE_F];

    const int tid  = threadIdx.x;
    const int warp = tid >> 5;
    const int lane = tid & 31;
    const int lr = lane >> 2;
    const int lc = lane & 3;

    const int wm = (warp & 3) * 32;
    const int wn = (warp >> 2) * 64;

    A += (size_t)blockIdx.y * 128 * K;
    B += (size_t)blockIdx.x * 128 * K;
    C += (size_t)blockIdx.y * 128 * N + blockIdx.x * 128;

    // loader: 1024 16B-chunks per matrix per slab (128 rows x 8 chunks);
    // 4 chunks per thread per matrix at rows r0, r0+32, r0+64, r0+96.
    const int r0 = tid >> 3;             // 0..31
    const int kc = (tid & 7) * 4;        // 0,4,...,28

    const uint32_t asBase = (uint32_t)__cvta_generic_to_shared(As);
    const uint32_t bsBase = (uint32_t)__cvta_generic_to_shared(Bs);

    const int nSlab = K / 32;

    auto load_slab = [&](int s, int buf) {
        const int gk = s * 32 + kc;
        const uint32_t ad = asBase + (uint32_t)(buf * STAGE_F * 4);
        const uint32_t bd = bsBase + (uint32_t)(buf * STAGE_F * 4);
        #pragma unroll
        for (int i = 0; i < 4; i++) {
            const int r = r0 + i * 32;
            cp_async16(ad + (uint32_t)((r * LDT_ + kc) * 4), A + (size_t)r * K + gk);
            cp_async16(bd + (uint32_t)((r * LDT_ + kc) * 4), B + (size_t)r * K + gk);
        }
    };

    // per-thread ldmatrix row addresses (float offsets within a stage)
    const int aoff = (wm + (lane & 15)) * LDT_ + ((lane >> 4) << 2);
    const int boff = (wn + ((lane >> 4) << 3) + (lane & 7)) * LDT_ + (((lane >> 3) & 1) << 2);

    float acc[2][8][4] = {};

    load_slab(0, 0); cp_commit();

    for (int s = 0; s < nSlab; s++) {
        const int cur = s & 1;

        // issue next slab's loads into the other buffer (free since the
        // end-of-previous-iteration barrier), giving the awaited group a
        // full compute phase of cover.
        if (s + 1 < nSlab) load_slab(s + 1, cur ^ 1);
        cp_commit();

        cp_wait<1>();        // slab s's group complete (s+1's may be pending)
        __syncthreads();

        const uint32_t aStage = asBase + (uint32_t)(cur * STAGE_F * 4);
        const uint32_t bStage = bsBase + (uint32_t)(cur * STAGE_F * 4);

        #pragma unroll
        for (int ks = 0; ks < 32; ks += 8) {
            uint32_t afr[2][4];
            #pragma unroll
            for (int mi = 0; mi < 2; mi++)
                ldsm_x4(afr[mi], aStage + (uint32_t)((aoff + mi * 16 * LDT_ + ks) * 4));
            uint32_t bfr[4][4];
            #pragma unroll
            for (int j = 0; j < 4; j++)
                ldsm_x4(bfr[j], bStage + (uint32_t)((boff + j * 16 * LDT_ + ks) * 4));
            #pragma unroll
            for (int mi = 0; mi < 2; mi++)
                #pragma unroll
                for (int j = 0; j < 4; j++) {
                    mma_tf32(acc[mi][2 * j],     afr[mi][0], afr[mi][1], afr[mi][2], afr[mi][3],
                             bfr[j][0], bfr[j][1]);
                    mma_tf32(acc[mi][2 * j + 1], afr[mi][0], afr[mi][1], afr[mi][2], afr[mi][3],
                             bfr[j][2], bfr[j][3]);
                }
        }
        __syncthreads();     // all warps done with buffer cur before it is
                             // overwritten by next iteration's load
    }

    #pragma unroll
    for (int mi = 0; mi < 2; mi++) {
        const int r = wm + 16 * mi + lr;
        #pragma unroll
        for (int ni = 0; ni < 8; ni++) {
            const int c0 = wn + 8 * ni + 2 * lc;
            *(float2*)(C + (size_t)r * N + c0)       = make_float2(acc[mi][ni][0], acc[mi][ni][1]);
            *(float2*)(C + (size_t)(r + 8) * N + c0) = make_float2(acc[mi][ni][2], acc[mi][ni][3]);
        }
    }
}

// ---------------------------------------------------------------------------
// FlashAttention, TF32 mma, exact (non-online) softmax.
// Block = 256 threads (8 warps), 128 query rows per block for one (b,h).
// P truncated to tf32 in place; l sums the same truncated values.
// ---------------------------------------------------------------------------
__global__ __launch_bounds__(256) void attn_mma_kernel(
    const float* __restrict__ qkv,
    float* __restrict__ attn_out)
{
    const int bh = blockIdx.y;
    const int b = bh / HEADS;
    const int h = bh % HEADS;
    const int qbase = blockIdx.x * 128;
    const int warp = threadIdx.x >> 5;
    const int lane = threadIdx.x & 31;
    const int lr = lane >> 2;
    const int lc = lane & 3;

    __shared__ float Ks[64][72];
    __shared__ float Vs[64][68];

    const float* base = qkv + (size_t)b * NSEQ * QKV_W;
    const float NEG_INF = __int_as_float(0xff800000);
    const float QSCALE = SCALE * LOG2E;

    const int diagKt = qbase + ((warp & 4) << 4);

    uint32_t qa[8][4];
    {
        const int r0 = qbase + warp * 16 + lr;
        const float* q0 = base + (size_t)r0 * QKV_W + h * DHEAD;
        const float* q1 = q0 + (size_t)8 * QKV_W;
        #pragma unroll
        for (int s = 0; s < 8; s++) {
            const int d0 = 8 * s + 2 * lc;
            qa[s][0] = cvt_tf32(q0[d0] * QSCALE);
            qa[s][1] = cvt_tf32(q1[d0] * QSCALE);
            qa[s][2] = cvt_tf32(q0[d0 + 1] * QSCALE);
            qa[s][3] = cvt_tf32(q1[d0 + 1] * QSCALE);
        }
    }

    float oa[8][4] = {};
    float l0 = 0.0f, l1 = 0.0f;

    for (int kt = 0; kt < NSEQ; kt += 64) {
        __syncthreads();

        #pragma unroll
        for (int it = 0; it < 4; it++) {
            const int idx = threadIdx.x + it * 256;
            const int r = idx >> 4;
            const int c = (idx & 15) * 4;
            const float* kr = base + (size_t)(kt + r) * QKV_W + INNER + h * DHEAD + c;
            const float* vr = kr + INNER;
            float4 kv = *(const float4*)kr;
            float4 vv = *(const float4*)vr;
            uint4 ku = make_uint4(cvt_tf32(kv.x), cvt_tf32(kv.y), cvt_tf32(kv.z), cvt_tf32(kv.w));
            uint4 vu = make_uint4(cvt_tf32(vv.x), cvt_tf32(vv.y), cvt_tf32(vv.z), cvt_tf32(vv.w));
            *(uint4*)(&Ks[r][c]) = ku;
            *(uint4*)(&Vs[r][c]) = vu;
        }
        __syncthreads();

        float sfr[8][4] = {};
        #pragma unroll
        for (int s = 0; s < 8; s++) {
            #pragma unroll
            for (int n = 0; n < 8; n++) {
                float2 kb = *(const float2*)(&Ks[8 * n + lr][8 * s + 2 * lc]);
                mma_tf32(sfr[n], qa[s][0], qa[s][1], qa[s][2], qa[s][3],
                         __float_as_uint(kb.x), __float_as_uint(kb.y));
            }
        }

        if (kt == diagKt) {
            const int rloc0 = 16 * (warp & 3) + lr;
            const int rloc1 = rloc0 + 8;
            #pragma unroll
            for (int n = 0; n < 8; n++) {
                const int col0 = 8 * n + 2 * lc;
                if (col0 == rloc0)     sfr[n][0] = NEG_INF;
                if (col0 + 1 == rloc0) sfr[n][1] = NEG_INF;
                if (col0 == rloc1)     sfr[n][2] = NEG_INF;
                if (col0 + 1 == rloc1) sfr[n][3] = NEG_INF;
            }
        }

        #pragma unroll
        for (int n = 0; n < 8; n++) {
            sfr[n][0] = trunc_tf32(exp2_fast(sfr[n][0]));
            sfr[n][1] = trunc_tf32(exp2_fast(sfr[n][1]));
            sfr[n][2] = trunc_tf32(exp2_fast(sfr[n][2]));
            sfr[n][3] = trunc_tf32(exp2_fast(sfr[n][3]));
            l0 += sfr[n][0] + sfr[n][1];
            l1 += sfr[n][2] + sfr[n][3];
        }

        #pragma unroll
        for (int s = 0; s < 8; s++) {
            const uint32_t a0 = __float_as_uint(sfr[s][0]);
            const uint32_t a1 = __float_as_uint(sfr[s][2]);
            const uint32_t a2 = __float_as_uint(sfr[s][1]);
            const uint32_t a3 = __float_as_uint(sfr[s][3]);
            #pragma unroll
            for (int n = 0; n < 8; n++) {
                const uint32_t vb0 = __float_as_uint(Vs[8 * s + 2 * lc][8 * n + lr]);
                const uint32_t vb1 = __float_as_uint(Vs[8 * s + 2 * lc + 1][8 * n + lr]);
                mma_tf32(oa[n], a0, a1, a2, a3, vb0, vb1);
            }
        }
    }

    l0 += __shfl_xor_sync(0xffffffffu, l0, 1);
    l0 += __shfl_xor_sync(0xffffffffu, l0, 2);
    l1 += __shfl_xor_sync(0xffffffffu, l1, 1);
    l1 += __shfl_xor_sync(0xffffffffu, l1, 2);
    const float inv0 = 1.0f / l0;
    const float inv1 = 1.0f / l1;

    const int row0 = qbase + 16 * warp + lr;
    float* o0 = attn_out + ((size_t)b * NSEQ + row0) * INNER + h * DHEAD;
    float* o1 = o0 + (size_t)8 * INNER;
    #pragma unroll
    for (int n = 0; n < 8; n++) {
        const int c = 8 * n + 2 * lc;
        *(float2*)(o0 + c) = make_float2(rnd_tf32(oa[n][0] * inv0), rnd_tf32(oa[n][1] * inv0));
        *(float2*)(o1 + c) = make_float2(rnd_tf32(oa[n][2] * inv1), rnd_tf32(oa[n][3] * inv1));
    }
}

// ---------------------------------------------------------------------------
extern "C" void kernel_launch(void* const* d_in, const int* in_sizes, int n_in,
                              void* d_out, int out_size)
{
    const float* x      = (const float*)d_in[0];
    const float* gamma  = (const float*)d_in[1];
    const float* beta   = (const float*)d_in[2];
    const float* w_qkv  = (const float*)d_in[3];
    const float* w_out  = (const float*)d_in[4];
    float* out = (float*)d_out;

    float *xn, *qkv, *attn, *wqkvT, *woutT;
    cudaGetSymbolAddress((void**)&xn,    g_xn);
    cudaGetSymbolAddress((void**)&qkv,   g_qkv);
    cudaGetSymbolAddress((void**)&attn,  g_attn);
    cudaGetSymbolAddress((void**)&wqkvT, g_wqkvT);
    cudaGetSymbolAddress((void**)&woutT, g_woutT);

    // 0) transpose + round weights: [K][N] -> [N][K] tf32
    {
        dim3 blk(32, 8);
        dim3 g1(QKV_W / 32, DIM / 32);
        transpose_round_kernel<<<g1, blk>>>(w_qkv, wqkvT, DIM, QKV_W);
        dim3 g2(DIM / 32, INNER / 32);
        transpose_round_kernel<<<g2, blk>>>(w_out, woutT, INNER, DIM);
    }

    // 1) LayerNorm (emits tf32-rounded)
    ln_kernel<<<ROWS, 256>>>(x, gamma, beta, xn);

    // 2) QKV projection: [4096,1024] @ [1024,3072]
    {
        dim3 grid(QKV_W / 128, ROWS / 128);
        tf32_gemm_ldsm<<<grid, 256>>>(ROWS, QKV_W, DIM, xn, wqkvT, qkv);
    }

    // 3) attention (128 q-rows per block)
    {
        dim3 grid(NSEQ / 128, BATCH * HEADS);
        attn_mma_kernel<<<grid, 256>>>(qkv, attn);
    }

    // 4) output projection: [4096,1024] @ [1024,1024]
    {
        dim3 grid(DIM / 128, ROWS / 128);
        tf32_gemm_ldsm<<<grid, 256>>>(ROWS, DIM, INNER, attn, woutT, out);
    }
}